// round 5
// baseline (speedup 1.0000x reference)
#include <cuda_runtime.h>
#include <cstdint>

// Unpool (2x2 max-unpool inverse scatter) as a single-pass gather/expand.
// Input:  val  fp32  [16,64,64,128], mask int32 same shape (flat out index).
// Output: out  fp32  [16,128,128,128].
//
// delta = mask - base ∈ {0, C, W2*C, W2*C+C} selects the quadrant.
// R4 measurements: latency-bound (DRAM 58.7%, L2 43.6%, issue 16.1% — nothing
// saturated). This version processes TWO adjacent-w pooled cells per thread
// (4 front-batched loads -> 2x MLP) and uses streaming cache hints (.cs) on
// all loads/stores since the kernel has zero data reuse.

namespace {
constexpr int B  = 16;
constexpr int H  = 64;
constexpr int W  = 64;
constexpr int C  = 128;
constexpr int H2 = H * 2;
constexpr int W2 = W * 2;
constexpr int C4 = C / 4;          // 32 float4 per channel row
constexpr int WP = W / 2;          // w-pairs per row
constexpr int NTHREADS_TOTAL = B * H * WP * C4;   // 1,048,576 = 2^20
constexpr int TPB = 256;

constexpr int D01 = C;             // (dh=0, dw=1)
constexpr int D10 = W2 * C;        // (dh=1, dw=0)
constexpr int D11 = W2 * C + C;    // (dh=1, dw=1)
}

__device__ __forceinline__ void expand_cell(const float4 v, const int4 m, int base,
                                            float4& o00, float4& o01,
                                            float4& o10, float4& o11) {
    const int d0 = m.x - base;
    const int d1 = m.y - (base + 1);
    const int d2 = m.z - (base + 2);
    const int d3 = m.w - (base + 3);

    o00.x = (d0 == 0)   ? v.x : 0.0f;
    o00.y = (d1 == 0)   ? v.y : 0.0f;
    o00.z = (d2 == 0)   ? v.z : 0.0f;
    o00.w = (d3 == 0)   ? v.w : 0.0f;

    o01.x = (d0 == D01) ? v.x : 0.0f;
    o01.y = (d1 == D01) ? v.y : 0.0f;
    o01.z = (d2 == D01) ? v.z : 0.0f;
    o01.w = (d3 == D01) ? v.w : 0.0f;

    o10.x = (d0 == D10) ? v.x : 0.0f;
    o10.y = (d1 == D10) ? v.y : 0.0f;
    o10.z = (d2 == D10) ? v.z : 0.0f;
    o10.w = (d3 == D10) ? v.w : 0.0f;

    o11.x = (d0 == D11) ? v.x : 0.0f;
    o11.y = (d1 == D11) ? v.y : 0.0f;
    o11.z = (d2 == D11) ? v.z : 0.0f;
    o11.w = (d3 == D11) ? v.w : 0.0f;
}

__global__ void __launch_bounds__(TPB)
unpool_expand2_kernel(const float4* __restrict__ val4,
                      const int4*   __restrict__ mask4,
                      float4*       __restrict__ out4) {
    const int tid = blockIdx.x * TPB + threadIdx.x;

    // tid bits: [0:5)=c4, [5:10)=wp, [10:16)=h, [16:20)=b
    const int c4 = tid & (C4 - 1);
    const int wp = (tid >> 5)  & (WP - 1);
    const int h  = (tid >> 10) & (H - 1);
    const int b  = tid >> 16;

    // input float4 indices of cells (b,h,2wp) and (b,h,2wp+1)
    const int in0 = ((b * H + h) * W + 2 * wp) * C4 + c4;
    const int in1 = in0 + C4;

    // 4 front-batched independent loads (2x MLP vs round 4), streaming hint
    const float4 v0 = __ldcs(&val4[in0]);
    const int4   m0 = __ldcs(&mask4[in0]);
    const float4 v1 = __ldcs(&val4[in1]);
    const int4   m1 = __ldcs(&mask4[in1]);

    // output float4 row base of (b, 2h, 4wp); cell1 starts 2 columns later
    const int cellO  = (b * H2 + 2 * h) * W2 + 4 * wp;
    const int base0  = cellO * C + (c4 << 2);
    const int base1  = base0 + 2 * C;

    float4 a00, a01, a10, a11, b00, b01, b10, b11;
    expand_cell(v0, m0, base0, a00, a01, a10, a11);
    expand_cell(v1, m1, base1, b00, b01, b10, b11);

    const int o = cellO * C4 + c4;    // float4 index of (b, 2h, 4wp, c4)
    const int R = W2 * C4;            // one output row of float4

    // top row: 4 coalesced 512B-per-warp stores spanning 2KB contiguous
    __stcs(&out4[o],              a00);   // (2h, 4wp  )
    __stcs(&out4[o + C4],         a01);   // (2h, 4wp+1)
    __stcs(&out4[o + 2 * C4],     b00);   // (2h, 4wp+2)
    __stcs(&out4[o + 3 * C4],     b01);   // (2h, 4wp+3)
    // bottom row
    __stcs(&out4[o + R],          a10);   // (2h+1, 4wp  )
    __stcs(&out4[o + R + C4],     a11);   // (2h+1, 4wp+1)
    __stcs(&out4[o + R + 2 * C4], b10);   // (2h+1, 4wp+2)
    __stcs(&out4[o + R + 3 * C4], b11);   // (2h+1, 4wp+3)
}

extern "C" void kernel_launch(void* const* d_in, const int* in_sizes, int n_in,
                              void* d_out, int out_size) {
    const float4* val4  = (const float4*)d_in[0];
    const int4*   mask4 = (const int4*)d_in[1];
    float4*       out4  = (float4*)d_out;

    const int nblocks = NTHREADS_TOTAL / TPB;  // 4096
    unpool_expand2_kernel<<<nblocks, TPB>>>(val4, mask4, out4);
}